// round 17
// baseline (speedup 1.0000x reference)
#include <cuda_runtime.h>
#include <cstdint>

// Problem constants (fixed by the dataset)
#define DD 16
#define BB 8
#define EE 2048
#define OO 2048

#define ECH    8                 // e's per chunk
#define NCHUNK (EE / ECH)        // 256
#define NTHREADS 128
#define OTILE  (NTHREADS * 4)    // 512 o's per block
#define NOT    (OO / OTILE)      // 4
#define PF     4                 // prefetch pipeline depth (one uint4 group)
#define NZERO  32                // blocks that zero `out` (32*128*4 floats = 16384)

// Single-wave flag barrier state (self-resetting each launch -> graph-safe)
__device__ int g_cnt  = 0;       // zeroing blocks finished
__device__ int g_done = 0;       // all zeroing done
__device__ int g_fin  = 0;       // blocks fully finished (for reset)

__global__ __launch_bounds__(NTHREADS, 7)   // 148*7 = 1036 >= 1024 -> single wave
void delta_synapse_main(const float* __restrict__ W,
                        const float* __restrict__ signs,
                        const float* __restrict__ Xd,
                        const float* __restrict__ Wshort,
                        const float* __restrict__ dmap,
                        float* __restrict__ out) {
    __shared__ float    coef[DD * BB][ECH];        // 4 KB: signed Xd*(Wshort+1)
    __shared__ float4   weffs[ECH][NTHREADS];      // 16 KB: raw W slice
    // Packed worklist word: ((d*EE + e) * OO) | bm   (off multiple of 2048)
    __shared__ __align__(16) uint32_t wl[ECH * DD + 2 * PF];
    __shared__ int   s_idx[ECH];
    __shared__ float s_pre[ECH];
    __shared__ int wl_n;

    const int tid   = threadIdx.x;
    const int chunk = blockIdx.x;                  // 0..255
    const int otile = blockIdx.y;                  // 0..3
    const int e0    = chunk * ECH;
    const int obase = otile * OTILE + tid * 4;

    // ---- Phase 0: designated blocks zero `out` (replaces the zero_out kernel).
    //      All 1024 blocks are co-resident (single wave), so a flag barrier is safe.
    if (otile == 0 && chunk < NZERO) {
        ((float4*)out)[chunk * NTHREADS + tid] = make_float4(0.f, 0.f, 0.f, 0.f);
        __threadfence();
        __syncthreads();
        if (tid == 0) {
            const int old = atomicAdd(&g_cnt, 1);
            if (old == NZERO - 1) {                // last zeroer: reset + release
                g_cnt = 0;
                atomicExch(&g_done, 1);
            }
        }
    }

    if (tid == 0) wl_n = 0;
    if (tid < ECH) s_idx[tid] = 0;
    __syncthreads();

    // ---- Phase 1: coef[d*8+b][el] = Xd * (Wshort + 1)  (1024 elems, 8/thread)
    #pragma unroll
    for (int r = 0; r < (DD * BB * ECH) / NTHREADS; r++) {
        const int idx = r * NTHREADS + tid;
        const int el  = idx & (ECH - 1);
        const int g   = idx >> 3;                   // d*8 + b
        const int gi  = g * EE + e0 + el;
        const float x = Xd[gi];
        coef[g][el] = x * (Wshort[gi] + 1.0f);
    }
    __syncthreads();

    // ---- Phase 2: one thread per (el,d) pair; warp-aggregated worklist append
    {
        const int el = tid & (ECH - 1);
        const int d  = tid >> 3;                    // 0..15
        unsigned bm = 0;
        #pragma unroll
        for (int b = 0; b < BB; b++)
            if (coef[d * BB + b][el] != 0.0f) bm |= 1u << b;
        const unsigned act  = __ballot_sync(0xffffffffu, bm != 0);
        const int      lane = tid & 31;
        int base = 0;
        if (lane == 0 && act) base = atomicAdd(&wl_n, __popc(act));
        base = __shfl_sync(0xffffffffu, base, 0);
        if (bm) {
            const int pos = base + __popc(act & ((1u << lane) - 1u));
            wl[pos] = ((uint32_t)(d * EE + e0 + el) * OO) | bm;
        }
    }
    __syncthreads();

    // ---- Pad sentinels: word 0 -> off 0, bm 0 -> skipped in the loop
    const int n0   = wl_n;
    const int npad = (n0 + PF - 1) & ~(PF - 1);    // multiple of 4 -> uint4 aligned
    if (tid < 2 * PF) wl[n0 + tid] = 0u;
    __syncthreads();

    // ---- Prologue: first group's words + their dmap LDGs (overlap Phase 3)
    const float* dbase = dmap + obase;
    float4 buf[PF];
    uint4  w4c = *(const uint4*)&wl[0];            // current group's words (regs)
    buf[0] = __ldcs((const float4*)(dbase + (w4c.x & ~2047u)));
    buf[1] = __ldcs((const float4*)(dbase + (w4c.y & ~2047u)));
    buf[2] = __ldcs((const float4*)(dbase + (w4c.z & ~2047u)));
    buf[3] = __ldcs((const float4*)(dbase + (w4c.w & ~2047u)));

    // ---- Phase 3a: raw W into smem; record any positive-W o per el (racy OK)
    #pragma unroll
    for (int el = 0; el < ECH; el++) {
        const float4 wv = __ldcs((const float4*)&W[(size_t)(e0 + el) * OO + obase]);
        weffs[el][tid] = wv;
        if (wv.x > 0.f || wv.y > 0.f || wv.z > 0.f || wv.w > 0.f) {
            const int c = wv.x > 0.f ? 0 : (wv.y > 0.f ? 1 : (wv.z > 0.f ? 2 : 3));
            s_idx[el] = obase + c;                  // benign race: any winner valid
        }
    }
    __syncthreads();

    // ---- Phase 3b: one scalar signs load per el (Weff == W * s_pre[e]).
    if (tid < ECH)
        s_pre[tid] = signs[(size_t)(e0 + tid) * OO + s_idx[tid]];
    __syncthreads();

    // ---- Fold s_pre into coef so the hot loop is unchanged
    #pragma unroll
    for (int el = 0; el < ECH; el++)
        coef[tid][el] *= s_pre[el];
    __syncthreads();

    float4 acc[BB];
    #pragma unroll
    for (int b = 0; b < BB; b++) acc[b] = make_float4(0.f, 0.f, 0.f, 0.f);

    // ---- Phase 4: PF-deep pipeline; one LDS.128 of packed words per group,
    //      current group's words carried in registers. (Unchanged from R16.)
    for (int i = 0; i < npad; i += PF) {
        const uint4 w4n = *(const uint4*)&wl[i + PF];   // next group's words
        #pragma unroll
        for (int j = 0; j < PF; j++) {
            const float4 dm = buf[j];

            const uint32_t wn = (j == 0) ? w4n.x : (j == 1) ? w4n.y
                              : (j == 2) ? w4n.z : w4n.w;
            buf[j] = __ldcs((const float4*)(dbase + (wn & ~2047u)));

            const uint32_t w = (j == 0) ? w4c.x : (j == 1) ? w4c.y
                             : (j == 2) ? w4c.z : w4c.w;
            unsigned bm = w & 255u;
            if (bm) {                               // warp-uniform; 0 only on sentinels
                const int el = (w >> 11) & 7;
                const int d  = w >> 22;
                const float4 wv = weffs[el][tid];   // raw W; sign folded in coef
                const float t0 = wv.x * dm.x;
                const float t1 = wv.y * dm.y;
                const float t2 = wv.z * dm.z;
                const float t3 = wv.w * dm.w;
                const float* crow = &coef[d * BB][el];  // +b*ECH per batch
                while (bm) {                        // avg ~1.2 active batches
                    const int b = __ffs(bm) - 1;
                    bm &= bm - 1;
                    const float c = crow[b * ECH];  // smem broadcast
                    switch (b) {                    // static acc indexing
                    case 0: acc[0].x += t0*c; acc[0].y += t1*c; acc[0].z += t2*c; acc[0].w += t3*c; break;
                    case 1: acc[1].x += t0*c; acc[1].y += t1*c; acc[1].z += t2*c; acc[1].w += t3*c; break;
                    case 2: acc[2].x += t0*c; acc[2].y += t1*c; acc[2].z += t2*c; acc[2].w += t3*c; break;
                    case 3: acc[3].x += t0*c; acc[3].y += t1*c; acc[3].z += t2*c; acc[3].w += t3*c; break;
                    case 4: acc[4].x += t0*c; acc[4].y += t1*c; acc[4].z += t2*c; acc[4].w += t3*c; break;
                    case 5: acc[5].x += t0*c; acc[5].y += t1*c; acc[5].z += t2*c; acc[5].w += t3*c; break;
                    case 6: acc[6].x += t0*c; acc[6].y += t1*c; acc[6].z += t2*c; acc[6].w += t3*c; break;
                    default: acc[7].x += t0*c; acc[7].y += t1*c; acc[7].z += t2*c; acc[7].w += t3*c; break;
                    }
                }
            }
        }
        w4c = w4n;                                  // carry next -> current (renaming)
    }

    // ---- Wait until `out` is zeroed (finished ~the whole mainloop ago -> free)
    if (tid == 0) {
        while (atomicAdd(&g_done, 0) == 0) __nanosleep(64);
    }
    __syncthreads();
    __threadfence();                                // order zero-stores before REDs

    // ---- Phase 5: reduce directly into out via vector REDG (no return value).
    #pragma unroll
    for (int b = 0; b < BB; b++) {
        float* dst = out + b * OO + obase;
        asm volatile("red.global.add.v4.f32 [%0], {%1, %2, %3, %4};"
                     :: "l"(dst),
                        "f"(acc[b].x), "f"(acc[b].y), "f"(acc[b].z), "f"(acc[b].w)
                     : "memory");
    }

    // ---- Self-reset for graph replay: last block clears the flags.
    if (tid == 0) {
        const int old = atomicAdd(&g_fin, 1);
        if (old == NCHUNK * NOT - 1) {              // 1023 -> this is the last block
            g_fin  = 0;
            g_done = 0;
        }
    }
}

extern "C" void kernel_launch(void* const* d_in, const int* in_sizes, int n_in,
                              void* d_out, int out_size) {
    (void)in_sizes; (void)n_in; (void)out_size;
    const float* W      = (const float*)d_in[0];
    const float* signs  = (const float*)d_in[1];
    const float* Xd     = (const float*)d_in[2];
    const float* Wshort = (const float*)d_in[3];
    const float* dmap   = (const float*)d_in[4];
    float* out = (float*)d_out;

    dim3 grid(NCHUNK, NOT);                       // 256 x 4 = 1024 blocks, 1 wave
    delta_synapse_main<<<grid, NTHREADS>>>(W, signs, Xd, Wshort, dmap, out);
}